// round 12
// baseline (speedup 1.0000x reference)
#include <cuda_runtime.h>

// Scratch via __device__ globals (no allocations allowed).
__device__ float    g_part[8192];
__device__ unsigned g_count = 0;   // self-resetting ticket -> deterministic per call

// MUFU sqrt: single instruction, max rel err ~2^-23, sqrt(0)=0.
__device__ __forceinline__ float fsqrt_approx(float x) {
    float r;
    asm("sqrt.approx.f32 %0, %1;" : "=f"(r) : "f"(x));
    return r;
}

// Shapes fixed: [8,3,16,256,256] fp32 -> 384 planes of 256x256. Row = 64 float4.
// FULL-ROW WARPS + ROLLING WINDOW, 4-ROW STRIPS (max occupancy):
//  - one warp covers a complete 256-wide row per step (lane l holds u=row[q=l],
//    v=row[q=l+32]; two 512B-coalesced LDG.128 per row).
//  - circular x-wraps: single shuffle per half-row. Each lane contributes a
//    pre-selected source (lane 0 contributes the OTHER half's .x), and
//    shfl(idx=(lane+1)&31) delivers both neighbor and wrap in one op.
//  - rolling 1-row-ahead window keeps loads in flight; ~32 regs -> 8 blocks/SM.
//  - strip = 4 rows => 24576 warps = 3072 blocks: SMs stay packed (occ ~90%),
//    fine-grained work stealing, row-reuse traffic 1.25x (absorbed by L2).
// TV magnitude: sqrt((x[h,w]-x[h,w+1])^2 + (x[h,w]-x[h+1,w])^2), circular.
__global__ void __launch_bounds__(256) tv_fused_kernel(const float4* __restrict__ in4,
                                                       float* __restrict__ out,
                                                       double inv_n) {
    const unsigned FULL = 0xFFFFFFFFu;
    const int lane = threadIdx.x & 31;
    const int wid  = threadIdx.x >> 5;
    const int gw   = blockIdx.x * 8 + wid;    // global warp id
    const int plane = gw >> 6;                // 64 strips per 256x256 plane
    const int h0    = (gw & 63) << 2;         // first row of this warp's 4-row strip
    const int nidx  = (lane + 1) & 31;        // shuffle source index (circular)

    const float4* __restrict__ p4 = in4 + ((long)plane << 14);  // 16384 float4/plane

    // Current row (h0)
    const int rb0 = h0 << 6;
    float4 uc = p4[rb0 + lane];
    float4 vc = p4[rb0 + 32 + lane];

    float acc = 0.0f;
    #pragma unroll
    for (int i = 0; i < 4; i++) {
        // Issue next-row loads FIRST (independent of current compute).
        const int rbn = (((h0 + i + 1) & 255) << 6);   // wraps only for last strip
        const float4 un = p4[rbn + lane];
        const float4 vn = p4[rbn + 32 + lane];

        // One shuffle per half-row: lane j contributes (j==0 ? other.x : own.x);
        // reading from lane (lane+1)&31 yields the right neighbor, including the
        // q31.w->q32.x and q63.w->q0.x circular wraps automatically.
        const float src_u = (lane == 0) ? vc.x : uc.x;
        const float src_v = (lane == 0) ? uc.x : vc.x;
        const float nu = __shfl_sync(FULL, src_u, nidx);
        const float nv = __shfl_sync(FULL, src_v, nidx);

        #define TV_PROC(a, nxt, c)                                         \
        {                                                                  \
            float dx0 = a.x - a.y,   dy0 = a.x - c.x;                      \
            float dx1 = a.y - a.z,   dy1 = a.y - c.y;                      \
            float dx2 = a.z - a.w,   dy2 = a.z - c.z;                      \
            float dx3 = a.w - (nxt), dy3 = a.w - c.w;                      \
            acc += fsqrt_approx(fmaf(dx0, dx0, dy0 * dy0));                \
            acc += fsqrt_approx(fmaf(dx1, dx1, dy1 * dy1));                \
            acc += fsqrt_approx(fmaf(dx2, dx2, dy2 * dy2));                \
            acc += fsqrt_approx(fmaf(dx3, dx3, dy3 * dy3));                \
        }
        TV_PROC(uc, nu, un)
        TV_PROC(vc, nv, vn)
        #undef TV_PROC

        uc = un; vc = vn;
    }

    // Warp reduce (8 warps per block)
    #pragma unroll
    for (int o = 16; o > 0; o >>= 1)
        acc += __shfl_xor_sync(FULL, acc, o);

    __shared__ float warpsum[8];
    __shared__ bool  s_last;
    if (lane == 0) warpsum[wid] = acc;
    if (threadIdx.x == 0) s_last = false;
    __syncthreads();

    if (threadIdx.x == 0) {
        float bsum = warpsum[0] + warpsum[1] + warpsum[2] + warpsum[3]
                   + warpsum[4] + warpsum[5] + warpsum[6] + warpsum[7];
        g_part[blockIdx.x] = bsum;
        __threadfence();
        unsigned ticket = atomicAdd(&g_count, 1u);
        if (ticket == gridDim.x - 1) s_last = true;
    }
    __syncthreads();

    // Last block to arrive reduces all partials and writes the output.
    if (s_last) {
        double dsum = 0.0;
        for (int i = threadIdx.x; i < (int)gridDim.x; i += 256)
            dsum += (double)g_part[i];
        #pragma unroll
        for (int o = 16; o > 0; o >>= 1)
            dsum += __shfl_xor_sync(FULL, dsum, o);
        __shared__ double dws[8];
        if (lane == 0) dws[wid] = dsum;
        __syncthreads();
        if (threadIdx.x == 0) {
            double ssum = dws[0] + dws[1] + dws[2] + dws[3]
                        + dws[4] + dws[5] + dws[6] + dws[7];
            out[0] = (float)(ssum * inv_n);
            g_count = 0;   // reset for next (graph-replayed) call
        }
    }
}

extern "C" void kernel_launch(void* const* d_in, const int* in_sizes, int n_in,
                              void* d_out, int out_size) {
    const float4* in4 = (const float4*)d_in[0];
    float* out = (float*)d_out;
    const long long n = in_sizes[0];              // 25,165,824
    // 384 planes * 64 strips/plane = 24576 warps = 3072 blocks of 8 warps
    const int threads = 256;
    const int blocks  = (int)(n / (threads * 32));  // 32 elems per thread -> 3072

    tv_fused_kernel<<<blocks, threads>>>(in4, out, 1.0 / (double)n);
}

// round 13
// speedup vs baseline: 1.2000x; 1.2000x over previous
#include <cuda_runtime.h>

// Scratch via __device__ globals (no allocations allowed).
__device__ float    g_part[8192];
__device__ unsigned g_count = 0;   // self-resetting ticket -> deterministic per call

// MUFU sqrt: single instruction, max rel err ~2^-23, sqrt(0)=0.
__device__ __forceinline__ float fsqrt_approx(float x) {
    float r;
    asm("sqrt.approx.f32 %0, %1;" : "=f"(r) : "f"(x));
    return r;
}

// Shapes fixed: [8,3,16,256,256] fp32 -> 384 planes of 256x256. Row = 64 float4.
// FULL-ROW WARPS + ROLLING WINDOW, 4-ROW STRIPS, 32-REG PIN:
//  - one warp covers a complete 256-wide row per step (lane l holds u=row[q=l],
//    v=row[q=l+32]; two 512B-coalesced LDG.128 per row).
//  - circular x-wraps are intra-warp shuffles only (R10 pattern, compiles to 32
//    regs): q31.w->q32.x = v.x of lane 0; q63.w->q0.x = u.x of lane 0.
//  - rolling 1-row-ahead window keeps next-row loads in flight during compute.
//  - __launch_bounds__(256, 8) pins <=32 regs -> 8 blocks/SM residency cap.
//  - strip = 4 rows => 3072 blocks: fine-grained dynamic balancing, small drain
//    tail. Duplicated boundary rows (1.25x L1 traffic) are L2 hits; DRAM-unique
//    traffic is unchanged, and L1 (19%) has headroom.
// TV magnitude: sqrt((x[h,w]-x[h,w+1])^2 + (x[h,w]-x[h+1,w])^2), circular.
__global__ void __launch_bounds__(256, 8) tv_fused_kernel(const float4* __restrict__ in4,
                                                          float* __restrict__ out,
                                                          double inv_n) {
    const unsigned FULL = 0xFFFFFFFFu;
    const int lane = threadIdx.x & 31;
    const int wid  = threadIdx.x >> 5;
    const int gw   = blockIdx.x * 8 + wid;    // global warp id
    const int plane = gw >> 6;                // 64 strips per 256x256 plane
    const int h0    = (gw & 63) << 2;         // first row of this warp's 4-row strip

    const float4* __restrict__ p4 = in4 + ((long)plane << 14);  // 16384 float4/plane

    // Current row (h0)
    const int rb0 = h0 << 6;
    float4 uc = p4[rb0 + lane];
    float4 vc = p4[rb0 + 32 + lane];

    float acc = 0.0f;
    #pragma unroll
    for (int i = 0; i < 4; i++) {
        // Issue next-row loads FIRST (independent of current compute).
        const int rbn = (((h0 + i + 1) & 255) << 6);   // wraps only for last strip
        const float4 un = p4[rbn + lane];
        const float4 vn = p4[rbn + 32 + lane];

        // Circular x-neighbors via shuffle (R10 pattern; all lanes execute both).
        const float su  = __shfl_down_sync(FULL, uc.x, 1);
        const float sv0 = __shfl_sync(FULL, vc.x, 0);
        const float nu  = (lane == 31) ? sv0 : su;
        const float sv  = __shfl_down_sync(FULL, vc.x, 1);
        const float su0 = __shfl_sync(FULL, uc.x, 0);
        const float nv  = (lane == 31) ? su0 : sv;

        #define TV_PROC(a, nxt, c)                                         \
        {                                                                  \
            float dx0 = a.x - a.y,   dy0 = a.x - c.x;                      \
            float dx1 = a.y - a.z,   dy1 = a.y - c.y;                      \
            float dx2 = a.z - a.w,   dy2 = a.z - c.z;                      \
            float dx3 = a.w - (nxt), dy3 = a.w - c.w;                      \
            acc += fsqrt_approx(fmaf(dx0, dx0, dy0 * dy0));                \
            acc += fsqrt_approx(fmaf(dx1, dx1, dy1 * dy1));                \
            acc += fsqrt_approx(fmaf(dx2, dx2, dy2 * dy2));                \
            acc += fsqrt_approx(fmaf(dx3, dx3, dy3 * dy3));                \
        }
        TV_PROC(uc, nu, un)
        TV_PROC(vc, nv, vn)
        #undef TV_PROC

        uc = un; vc = vn;
    }

    // Warp reduce (8 warps per block)
    #pragma unroll
    for (int o = 16; o > 0; o >>= 1)
        acc += __shfl_xor_sync(FULL, acc, o);

    __shared__ float warpsum[8];
    __shared__ bool  s_last;
    if (lane == 0) warpsum[wid] = acc;
    if (threadIdx.x == 0) s_last = false;
    __syncthreads();

    if (threadIdx.x == 0) {
        float bsum = warpsum[0] + warpsum[1] + warpsum[2] + warpsum[3]
                   + warpsum[4] + warpsum[5] + warpsum[6] + warpsum[7];
        g_part[blockIdx.x] = bsum;
        __threadfence();
        unsigned ticket = atomicAdd(&g_count, 1u);
        if (ticket == gridDim.x - 1) s_last = true;
    }
    __syncthreads();

    // Last block to arrive reduces all partials and writes the output.
    if (s_last) {
        double dsum = 0.0;
        for (int i = threadIdx.x; i < (int)gridDim.x; i += 256)
            dsum += (double)g_part[i];
        #pragma unroll
        for (int o = 16; o > 0; o >>= 1)
            dsum += __shfl_xor_sync(FULL, dsum, o);
        __shared__ double dws[8];
        if (lane == 0) dws[wid] = dsum;
        __syncthreads();
        if (threadIdx.x == 0) {
            double ssum = dws[0] + dws[1] + dws[2] + dws[3]
                        + dws[4] + dws[5] + dws[6] + dws[7];
            out[0] = (float)(ssum * inv_n);
            g_count = 0;   // reset for next (graph-replayed) call
        }
    }
}

extern "C" void kernel_launch(void* const* d_in, const int* in_sizes, int n_in,
                              void* d_out, int out_size) {
    const float4* in4 = (const float4*)d_in[0];
    float* out = (float*)d_out;
    const long long n = in_sizes[0];              // 25,165,824
    // 384 planes * 64 strips/plane = 24576 warps = 3072 blocks of 8 warps
    const int threads = 256;
    const int blocks  = (int)(n / (threads * 32));  // 32 elems per thread -> 3072

    tv_fused_kernel<<<blocks, threads>>>(in4, out, 1.0 / (double)n);
}

// round 14
// speedup vs baseline: 1.3196x; 1.0997x over previous
#include <cuda_runtime.h>

// Scratch via __device__ globals (no allocations allowed).
__device__ float    g_part[8192];
__device__ unsigned g_count = 0;   // self-resetting ticket -> deterministic per call

// MUFU sqrt: single instruction, max rel err ~2^-23, sqrt(0)=0.
__device__ __forceinline__ float fsqrt_approx(float x) {
    float r;
    asm("sqrt.approx.f32 %0, %1;" : "=f"(r) : "f"(x));
    return r;
}

// Shapes fixed: [8,3,16,256,256] fp32 -> 384 planes of 256x256. Row = 64 float4.
// FULL-ROW WARPS + TRUE 2-STAGE SOFTWARE PIPELINE, 8-ROW STRIPS:
//  - one warp covers a complete 256-wide row per step (lane l holds u=row[q=l],
//    v=row[q=l+32]; two 512B-coalesced LDG.128 per row).
//  - circular x-wraps are intra-warp shuffles only (q31.w->q32.x = v.x lane 0;
//    q63.w->q0.x = u.x lane 0) -> zero divergent scalar loads.
//  - PIPELINE: rows i and i+1 are register-resident; row i+2's loads are issued
//    BEFORE row i's compute. Unlike the old "rolling window" (whose load was
//    consumed in the same iteration), every consumed load here has a full
//    iteration of compute + the other warps to cover its latency.
//  - __launch_bounds__(256, 6): 42-reg cap fits the 6-float4 live set without
//    spills; occ ~75% with MLP 4 per thread (the frontier point between
//    R10 occ83/MLP2 = 18.6us and R9 occ45/MLP10 = 22.8us).
// TV magnitude: sqrt((x[h,w]-x[h,w+1])^2 + (x[h,w]-x[h+1,w])^2), circular.
__global__ void __launch_bounds__(256, 6) tv_fused_kernel(const float4* __restrict__ in4,
                                                          float* __restrict__ out,
                                                          double inv_n) {
    const unsigned FULL = 0xFFFFFFFFu;
    const int lane = threadIdx.x & 31;
    const int wid  = threadIdx.x >> 5;
    const int gw   = blockIdx.x * 8 + wid;    // global warp id
    const int plane = gw >> 5;                // 32 strips per 256x256 plane
    const int h0    = (gw & 31) << 3;         // first row of this warp's 8-row strip

    const float4* __restrict__ p4 = in4 + ((long)plane << 14);  // 16384 float4/plane

    // Preload rows h0 and h0+1 (h0+1 never wraps: h0 <= 248).
    const int rb0 = h0 << 6;
    float4 uc = p4[rb0 + lane];
    float4 vc = p4[rb0 + 32 + lane];
    float4 un = p4[rb0 + 64 + lane];
    float4 vn = p4[rb0 + 96 + lane];

    float acc = 0.0f;
    #pragma unroll
    for (int i = 0; i < 8; i++) {
        // Stage 1: issue row i+2's loads (latency covered by this iteration's
        // compute; only the last compute row wraps circularly).
        float4 up, vp;
        if (i < 7) {
            const int rbn = ((h0 + i + 2) & 255) << 6;
            up = p4[rbn + lane];
            vp = p4[rbn + 32 + lane];
        }

        // Circular x-neighbors of row i via shuffle (all lanes execute both).
        const float su  = __shfl_down_sync(FULL, uc.x, 1);
        const float sv0 = __shfl_sync(FULL, vc.x, 0);
        const float nu  = (lane == 31) ? sv0 : su;
        const float sv  = __shfl_down_sync(FULL, vc.x, 1);
        const float su0 = __shfl_sync(FULL, uc.x, 0);
        const float nv  = (lane == 31) ? su0 : sv;

        // Stage 2: compute row i from resident rows i (uc/vc) and i+1 (un/vn).
        #define TV_PROC(a, nxt, c)                                         \
        {                                                                  \
            float dx0 = a.x - a.y,   dy0 = a.x - c.x;                      \
            float dx1 = a.y - a.z,   dy1 = a.y - c.y;                      \
            float dx2 = a.z - a.w,   dy2 = a.z - c.z;                      \
            float dx3 = a.w - (nxt), dy3 = a.w - c.w;                      \
            acc += fsqrt_approx(fmaf(dx0, dx0, dy0 * dy0));                \
            acc += fsqrt_approx(fmaf(dx1, dx1, dy1 * dy1));                \
            acc += fsqrt_approx(fmaf(dx2, dx2, dy2 * dy2));                \
            acc += fsqrt_approx(fmaf(dx3, dx3, dy3 * dy3));                \
        }
        TV_PROC(uc, nu, un)
        TV_PROC(vc, nv, vn)
        #undef TV_PROC

        // Shift pipeline.
        uc = un; vc = vn;
        if (i < 7) { un = up; vn = vp; }
    }

    // Warp reduce (8 warps per block)
    #pragma unroll
    for (int o = 16; o > 0; o >>= 1)
        acc += __shfl_xor_sync(FULL, acc, o);

    __shared__ float warpsum[8];
    __shared__ bool  s_last;
    if (lane == 0) warpsum[wid] = acc;
    if (threadIdx.x == 0) s_last = false;
    __syncthreads();

    if (threadIdx.x == 0) {
        float bsum = warpsum[0] + warpsum[1] + warpsum[2] + warpsum[3]
                   + warpsum[4] + warpsum[5] + warpsum[6] + warpsum[7];
        g_part[blockIdx.x] = bsum;
        __threadfence();
        unsigned ticket = atomicAdd(&g_count, 1u);
        if (ticket == gridDim.x - 1) s_last = true;
    }
    __syncthreads();

    // Last block to arrive reduces all partials and writes the output.
    if (s_last) {
        double dsum = 0.0;
        for (int i = threadIdx.x; i < (int)gridDim.x; i += 256)
            dsum += (double)g_part[i];
        #pragma unroll
        for (int o = 16; o > 0; o >>= 1)
            dsum += __shfl_xor_sync(FULL, dsum, o);
        __shared__ double dws[8];
        if (lane == 0) dws[wid] = dsum;
        __syncthreads();
        if (threadIdx.x == 0) {
            double ssum = dws[0] + dws[1] + dws[2] + dws[3]
                        + dws[4] + dws[5] + dws[6] + dws[7];
            out[0] = (float)(ssum * inv_n);
            g_count = 0;   // reset for next (graph-replayed) call
        }
    }
}

extern "C" void kernel_launch(void* const* d_in, const int* in_sizes, int n_in,
                              void* d_out, int out_size) {
    const float4* in4 = (const float4*)d_in[0];
    float* out = (float*)d_out;
    const long long n = in_sizes[0];              // 25,165,824
    // 384 planes * 32 strips/plane = 12288 warps = 1536 blocks of 8 warps
    const int threads = 256;
    const int blocks  = (int)(n / (threads * 64));  // 64 elems per thread -> 1536

    tv_fused_kernel<<<blocks, threads>>>(in4, out, 1.0 / (double)n);
}